// round 1
// baseline (speedup 1.0000x reference)
#include <cuda_runtime.h>
#include <cstdint>

// ---------------------------------------------------------------------------
// SO3Linear (L=3): out[b,M,co] = sum_{g: seg2[g]=M} ( inter[b,g,:] @ W[l_ind[g]] )
// inter[b,g,ci]   = sum_{nz: seg1[nz]=g} CG[nz]*sh[b,M2[nz]]*x[b,M1[nz],ci]
//
// Shapes (fixed by problem): B=1024, NUM_ORDERS=16, C_IN=C_OUT=256,
//                            G=156 groups, nnz=478, 34 distinct weights.
// seg1 and seg2 are nondecreasing by construction -> group nz-ranges and
// per-output-order group ranges are contiguous.
// ---------------------------------------------------------------------------

#define B_MAX    1024
#define NORD     16
#define CI       256
#define CO       256
#define G_MAX    156
#define NNZ_MAX  512

#define TB   64    // batch rows per GEMM block
#define TCO  128   // output cols per GEMM block
#define TK   16    // k-slab

// scratch: inter laid out [g][b][ci]  (contiguous b*ci per group -> coalesced GEMM loads)
__device__ float g_inter[(size_t)G_MAX * B_MAX * CI];
__device__ int   g_gs[G_MAX + 1];   // nz start offset per group
__device__ int   g_mg[NORD + 1];    // group start offset per output order M

// ---------------------------------------------------------------------------
// packed f32x2 helpers (sm_100+): doubles FFMA throughput vs 3-reg FFMA
// ---------------------------------------------------------------------------
__device__ __forceinline__ unsigned long long packdup(float a) {
    unsigned long long r;
    asm("mov.b64 %0, {%1, %1};" : "=l"(r) : "f"(a));
    return r;
}
__device__ __forceinline__ void unpack2(unsigned long long v, float& lo, float& hi) {
    asm("mov.b64 {%0, %1}, %2;" : "=f"(lo), "=f"(hi) : "l"(v));
}
__device__ __forceinline__ void ffma2(unsigned long long& d,
                                      unsigned long long a,
                                      unsigned long long b) {
    asm("fma.rn.f32x2 %0, %1, %2, %0;" : "+l"(d) : "l"(a), "l"(b));
}

// ---------------------------------------------------------------------------
// Kernel 0: derive contiguous range tables from seg1/seg2 (both nondecreasing)
// ---------------------------------------------------------------------------
__global__ void setup_offsets(const int* __restrict__ seg1,
                              const int* __restrict__ seg2,
                              int nnz, int G) {
    int tid = threadIdx.x;
    for (int i = tid; i < nnz; i += blockDim.x) {
        if (i == 0) g_gs[seg1[0]] = 0;
        else if (seg1[i] != seg1[i - 1]) g_gs[seg1[i]] = i;
    }
    for (int i = tid; i < G; i += blockDim.x) {
        if (i == 0) g_mg[seg2[0]] = 0;
        else if (seg2[i] != seg2[i - 1]) g_mg[seg2[i]] = i;
    }
    if (tid == 0) { g_gs[G] = nnz; g_mg[NORD] = G; }
}

// ---------------------------------------------------------------------------
// Kernel 1: build inter[g][b][ci]. One block per b; 256 threads = one per ci.
// x[b] (16KB) stays L1-resident; writes are fully coalesced.
// ---------------------------------------------------------------------------
__global__ __launch_bounds__(256) void build_inter(
    const float* __restrict__ x,
    const float* __restrict__ sh,
    const float* __restrict__ CG,
    const int* __restrict__ M1,
    const int* __restrict__ M2,
    int nnz, int G, int Bn) {

    __shared__ float coefs[NNZ_MAX];
    __shared__ int   m1s[NNZ_MAX];
    __shared__ int   gs_s[G_MAX + 1];

    const int b   = blockIdx.x;
    const int tid = threadIdx.x;

    for (int i = tid; i < nnz; i += blockDim.x) {
        coefs[i] = CG[i] * sh[b * NORD + M2[i]];
        m1s[i]   = M1[i];
    }
    for (int i = tid; i <= G; i += blockDim.x) gs_s[i] = g_gs[i];
    __syncthreads();

    const float* xb = x + (size_t)b * NORD * CI;
    const int ci = tid;

    for (int g = 0; g < G; ++g) {
        float acc = 0.f;
        const int e = gs_s[g + 1];
        for (int idx = gs_s[g]; idx < e; ++idx)
            acc = fmaf(coefs[idx], xb[m1s[idx] * CI + ci], acc);
        g_inter[((size_t)g * Bn + b) * CI + ci] = acc;
    }
}

// ---------------------------------------------------------------------------
// Kernel 2: grouped GEMM + scatter. Block owns (b_tile=64, M, co_tile=128);
// accumulates over all groups g in [g_mg[M], g_mg[M+1]) so out is written
// exactly once, no atomics. Inner math on packed f32x2 FFMA.
// ---------------------------------------------------------------------------
__global__ __launch_bounds__(256) void gemm_scatter(
    const float* __restrict__ weight,
    const int* __restrict__ l_ind,
    float* __restrict__ out,
    int Bn) {

    __shared__ float As[TK][TB];    // inter slab, transposed (k-major)
    __shared__ float Bs[TK][TCO];   // weight slab

    const int co0 = blockIdx.x * TCO;
    const int b0  = blockIdx.y * TB;
    const int M   = blockIdx.z;
    const int tid = threadIdx.x;
    const int tx  = tid & 15;   // 16 cols of threads -> 8 co each
    const int ty  = tid >> 4;   // 16 rows of threads -> 4 b each

    // 4 b-rows x 8 co = 4 x 4 packed f32x2 accumulators
    unsigned long long acc[4][4];
#pragma unroll
    for (int r = 0; r < 4; ++r)
#pragma unroll
        for (int p = 0; p < 4; ++p) acc[r][p] = 0ull;

    const int gbeg = g_mg[M];
    const int gend = g_mg[M + 1];

    for (int g = gbeg; g < gend; ++g) {
        const float* Wg = weight + (size_t)l_ind[g] * CI * CO;
        const float* Ig = g_inter + ((size_t)g * Bn + b0) * CI;

        for (int k0 = 0; k0 < CI; k0 += TK) {
            // load As (64 rows x 16 k), store transposed
            {
                const int r  = tid >> 2;
                const int kq = (tid & 3) * 4;
                float4 v = *reinterpret_cast<const float4*>(Ig + (size_t)r * CI + k0 + kq);
                As[kq + 0][r] = v.x;
                As[kq + 1][r] = v.y;
                As[kq + 2][r] = v.z;
                As[kq + 3][r] = v.w;
            }
            // load Bs (16 k x 128 co)
            {
                const int kk = tid >> 4;
                const int c  = (tid & 15) * 8;
                const float* wp = Wg + (size_t)(k0 + kk) * CO + co0 + c;
                *reinterpret_cast<float4*>(&Bs[kk][c])     = *reinterpret_cast<const float4*>(wp);
                *reinterpret_cast<float4*>(&Bs[kk][c + 4]) = *reinterpret_cast<const float4*>(wp + 4);
            }
            __syncthreads();

#pragma unroll
            for (int kk = 0; kk < TK; ++kk) {
                float4 av = *reinterpret_cast<const float4*>(&As[kk][ty * 4]);
                unsigned long long a2[4];
                a2[0] = packdup(av.x);
                a2[1] = packdup(av.y);
                a2[2] = packdup(av.z);
                a2[3] = packdup(av.w);

                float4 bv0 = *reinterpret_cast<const float4*>(&Bs[kk][tx * 8]);
                float4 bv1 = *reinterpret_cast<const float4*>(&Bs[kk][tx * 8 + 4]);
                unsigned long long bp[4];
                bp[0] = reinterpret_cast<const unsigned long long*>(&bv0)[0];
                bp[1] = reinterpret_cast<const unsigned long long*>(&bv0)[1];
                bp[2] = reinterpret_cast<const unsigned long long*>(&bv1)[0];
                bp[3] = reinterpret_cast<const unsigned long long*>(&bv1)[1];

#pragma unroll
                for (int r = 0; r < 4; ++r)
#pragma unroll
                    for (int p = 0; p < 4; ++p)
                        ffma2(acc[r][p], a2[r], bp[p]);
            }
            __syncthreads();
        }
    }

    // write out[b0+ty*4+r][M][co0+tx*8 .. +7], exactly once per element
#pragma unroll
    for (int r = 0; r < 4; ++r) {
        float c[8];
#pragma unroll
        for (int p = 0; p < 4; ++p) unpack2(acc[r][p], c[2 * p], c[2 * p + 1]);
        float* op = out + ((size_t)(b0 + ty * 4 + r) * NORD + M) * CO + co0 + tx * 8;
        *reinterpret_cast<float4*>(op)     = make_float4(c[0], c[1], c[2], c[3]);
        *reinterpret_cast<float4*>(op + 4) = make_float4(c[4], c[5], c[6], c[7]);
    }
}

// ---------------------------------------------------------------------------
// Inputs (metadata order): x, sh, weight, CG_vals, M1, M2, seg1, l_ind, seg2,
//                          num_orders_out
// ---------------------------------------------------------------------------
extern "C" void kernel_launch(void* const* d_in, const int* in_sizes, int n_in,
                              void* d_out, int out_size) {
    const float* x      = (const float*)d_in[0];
    const float* sh     = (const float*)d_in[1];
    const float* weight = (const float*)d_in[2];
    const float* CG     = (const float*)d_in[3];
    const int*   M1     = (const int*)d_in[4];
    const int*   M2     = (const int*)d_in[5];
    const int*   seg1   = (const int*)d_in[6];
    const int*   l_ind  = (const int*)d_in[7];
    const int*   seg2   = (const int*)d_in[8];
    float*       out    = (float*)d_out;

    const int nnz = in_sizes[4];              // 478
    const int G   = in_sizes[7];              // 156
    const int Bn  = in_sizes[1] / NORD;       // 1024

    setup_offsets<<<1, 256>>>(seg1, seg2, nnz, G);
    build_inter<<<Bn, 256>>>(x, sh, CG, M1, M2, nnz, G, Bn);

    dim3 grid(CO / TCO, Bn / TB, NORD);       // (2, 16, 16) = 512 blocks
    gemm_scatter<<<grid, 256>>>(weight, l_ind, out, Bn);
}

// round 3
// speedup vs baseline: 2.0999x; 2.0999x over previous
#include <cuda_runtime.h>
#include <cuda_bf16.h>
#include <cstdint>

// ---------------------------------------------------------------------------
// SO3Linear (L=3, B=1024, C=256) via bf16 split-precision mma.sync GEMM.
// (tcgen05 is unavailable: harness PTX target is compute_103, no 'a' feature)
//
//  K0 setup_offsets : contiguous range tables from seg1/seg2 (nondecreasing)
//  K1 wsplit        : W[w][ci][co] fp32 -> Wt{h,l}[w][co][ci] bf16
//  K2 build_inter   : inter[g][b][ci] fp32 -> A{h,l}[g][b][ci] bf16
//  K3 so3_mma       : per CTA (64 b-rows, order M, full co=256):
//                     fp32 accum of sum_g [Ah@Wh + Al@Wh + Ah@Wl]
//                     -> rel err ~1e-5. cp.async double buffer + ldmatrix.
// ---------------------------------------------------------------------------

#define NORD     16
#define CI       256
#define CO       256
#define G_MAX    156
#define NNZ_MAX  512
#define NW_MAX   40
#define B_MAX    1024

// ---- device scratch ----
__device__ __nv_bfloat16 g_ah[(size_t)G_MAX * B_MAX * CI];
__device__ __nv_bfloat16 g_al[(size_t)G_MAX * B_MAX * CI];
__device__ __nv_bfloat16 g_wth[(size_t)NW_MAX * CO * CI];
__device__ __nv_bfloat16 g_wtl[(size_t)NW_MAX * CO * CI];
__device__ int g_gs[G_MAX + 1];
__device__ int g_mg[NORD + 1];

#define SWZ(o) ((o) ^ (((o) >> 3) & 0x70))

__device__ __forceinline__ uint32_t smem_u32(const void* p) {
    uint32_t a;
    asm("{ .reg .u64 t; cvta.to.shared.u64 t, %1; cvt.u32.u64 %0, t; }" : "=r"(a) : "l"(p));
    return a;
}
__device__ __forceinline__ void cp16(uint32_t dst, const void* src) {
    asm volatile("cp.async.cg.shared.global [%0], [%1], 16;" :: "r"(dst), "l"(src) : "memory");
}
#define CP_COMMIT()  asm volatile("cp.async.commit_group;" ::: "memory")
#define CP_WAIT(N)   asm volatile("cp.async.wait_group %0;" :: "n"(N) : "memory")

__device__ __forceinline__ void ldsm4(uint32_t r[4], uint32_t addr) {
    asm volatile("ldmatrix.sync.aligned.m8n8.x4.shared.b16 {%0,%1,%2,%3}, [%4];"
                 : "=r"(r[0]), "=r"(r[1]), "=r"(r[2]), "=r"(r[3]) : "r"(addr));
}
__device__ __forceinline__ void mma16816(float c[4], const uint32_t a[4],
                                         uint32_t b0, uint32_t b1) {
    asm volatile(
        "mma.sync.aligned.m16n8k16.row.col.f32.bf16.bf16.f32 "
        "{%0,%1,%2,%3}, {%4,%5,%6,%7}, {%8,%9}, {%0,%1,%2,%3};"
        : "+f"(c[0]), "+f"(c[1]), "+f"(c[2]), "+f"(c[3])
        : "r"(a[0]), "r"(a[1]), "r"(a[2]), "r"(a[3]), "r"(b0), "r"(b1));
}

// ---------------------------------------------------------------------------
// K0: range tables
// ---------------------------------------------------------------------------
__global__ void setup_offsets(const int* __restrict__ seg1,
                              const int* __restrict__ seg2,
                              int nnz, int G) {
    int tid = threadIdx.x;
    for (int i = tid; i < nnz; i += blockDim.x) {
        if (i == 0) g_gs[seg1[0]] = 0;
        else if (seg1[i] != seg1[i - 1]) g_gs[seg1[i]] = i;
    }
    for (int i = tid; i < G; i += blockDim.x) {
        if (i == 0) g_mg[seg2[0]] = 0;
        else if (seg2[i] != seg2[i - 1]) g_mg[seg2[i]] = i;
    }
    if (tid == 0) { g_gs[G] = nnz; g_mg[NORD] = G; }
}

// ---------------------------------------------------------------------------
// K1: transpose + split weights: W[w][ci][co] -> Wt{h,l}[w][co][ci]
// ---------------------------------------------------------------------------
__global__ __launch_bounds__(256) void wsplit(const float* __restrict__ weight) {
    __shared__ float tile[32][33];
    const int w  = blockIdx.z;
    const int bx = blockIdx.x;
    const int by = blockIdx.y;
    const int tx = threadIdx.x & 31;
    const int ty = threadIdx.x >> 5;

    const float* in = weight + (size_t)w * CI * CO;
#pragma unroll
    for (int j = 0; j < 4; ++j) {
        int r = ty + 8 * j;
        tile[r][tx] = in[(size_t)(by * 32 + r) * CO + bx * 32 + tx];
    }
    __syncthreads();
#pragma unroll
    for (int j = 0; j < 4; ++j) {
        int r = ty + 8 * j;
        float v = tile[tx][r];
        __nv_bfloat16 h = __float2bfloat16(v);
        float lo = v - __bfloat162float(h);
        size_t o = ((size_t)w * CO + (bx * 32 + r)) * CI + by * 32 + tx;
        g_wth[o] = h;
        g_wtl[o] = __float2bfloat16(lo);
    }
}

// ---------------------------------------------------------------------------
// K2: build inter, split into bf16 hi/lo planes. One block per b.
// ---------------------------------------------------------------------------
__global__ __launch_bounds__(256) void build_inter(
    const float* __restrict__ x,
    const float* __restrict__ sh,
    const float* __restrict__ CG,
    const int* __restrict__ M1,
    const int* __restrict__ M2,
    int nnz, int G, int Bn) {

    __shared__ float coefs[NNZ_MAX];
    __shared__ int   m1s[NNZ_MAX];
    __shared__ int   gs_s[G_MAX + 1];

    const int b   = blockIdx.x;
    const int tid = threadIdx.x;

    for (int i = tid; i < nnz; i += blockDim.x) {
        coefs[i] = CG[i] * sh[b * NORD + M2[i]];
        m1s[i]   = M1[i];
    }
    for (int i = tid; i <= G; i += blockDim.x) gs_s[i] = g_gs[i];
    __syncthreads();

    const float* xb = x + (size_t)b * NORD * CI;
    const int ci = tid;

    for (int g = 0; g < G; ++g) {
        float acc = 0.f;
        const int e = gs_s[g + 1];
        for (int idx = gs_s[g]; idx < e; ++idx)
            acc = fmaf(coefs[idx], xb[m1s[idx] * CI + ci], acc);
        __nv_bfloat16 h = __float2bfloat16(acc);
        float lo = acc - __bfloat162float(h);
        size_t o = ((size_t)g * Bn + b) * CI + ci;
        g_ah[o] = h;
        g_al[o] = __float2bfloat16(lo);
    }
}

// ---------------------------------------------------------------------------
// K3: mma.sync GEMM. Grid (Bn/64, NORD), 256 threads (8 warps: 2m x 4n).
// Block tile: 64(b) x 256(co), K-tile 64. Stage (80KB): Ah 8K|Al 8K|Wh 32K|Wl 32K
// Double-buffered with cp.async.
// ---------------------------------------------------------------------------
#define KT          64
#define STAGE_BYTES 81920
#define OFF_AL      8192
#define OFF_WH      16384
#define OFF_WL      49152
#define SMEM_DYN    (2 * STAGE_BYTES + 1024)

__device__ __forceinline__ void load_stage(uint32_t st,
                                           const char* gAh, const char* gAl,
                                           const char* gWh, const char* gWl,
                                           int tid) {
#pragma unroll
    for (int i = 0; i < 2; ++i) {           // A planes: 64 rows x 8 chunks
        int idx = tid + i * 256;
        int r = idx >> 3, c = idx & 7;
        uint32_t so = SWZ(r * 128 + c * 16);
        size_t go = (size_t)r * (CI * 2) + c * 16;
        cp16(st + so,          gAh + go);
        cp16(st + OFF_AL + so, gAl + go);
    }
#pragma unroll
    for (int i = 0; i < 8; ++i) {           // W planes: 256 rows x 8 chunks
        int idx = tid + i * 256;
        int r = idx >> 3, c = idx & 7;
        uint32_t so = SWZ(r * 128 + c * 16);
        size_t go = (size_t)r * (CI * 2) + c * 16;
        cp16(st + OFF_WH + so, gWh + go);
        cp16(st + OFF_WL + so, gWl + go);
    }
}

__global__ __launch_bounds__(256, 1) void so3_mma(
    const int* __restrict__ l_ind,
    float* __restrict__ out,
    int Bn) {

    extern __shared__ char smem[];
    const uint32_t sb   = smem_u32(smem);
    const uint32_t base = (sb + 1023) & ~1023u;

    const int tid  = threadIdx.x;
    const int wid  = tid >> 5;
    const int lane = tid & 31;
    const int wm   = wid & 1;          // 2 m-warps
    const int wn   = wid >> 1;         // 4 n-warps

    const int b0 = blockIdx.x * 64;
    const int M  = blockIdx.y;
    const int gbeg = g_mg[M];
    const int gend = g_mg[M + 1];
    const int T = (gend - gbeg) * (CI / KT);   // k-tiles

    float acc[2][8][4];
#pragma unroll
    for (int i = 0; i < 2; ++i)
#pragma unroll
        for (int j = 0; j < 8; ++j)
#pragma unroll
            for (int q = 0; q < 4; ++q) acc[i][j][q] = 0.f;

    // per-tile source pointers
    auto srcA = [&](int t, const __nv_bfloat16* plane) -> const char* {
        int g = gbeg + (t >> 2), kc = t & 3;
        return (const char*)plane + (((size_t)g * Bn + b0) * CI + kc * KT) * 2;
    };
    auto srcW = [&](int t, const __nv_bfloat16* plane) -> const char* {
        int g = gbeg + (t >> 2), kc = t & 3;
        int w = __ldg(l_ind + g);
        return (const char*)plane + (((size_t)w * CO) * CI + kc * KT) * 2;
    };

    // prologue
    load_stage(base, srcA(0, g_ah), srcA(0, g_al), srcW(0, g_wth), srcW(0, g_wtl), tid);
    CP_COMMIT();

    // ldmatrix lane addressing (fixed per thread)
    const int arow = wm * 32 + (lane & 15);
    const int acol = (lane >> 4) * 16;
    const int wrow = wn * 64 + (lane & 7) + ((lane >> 4) << 3);
    const int wcol = ((lane >> 3) & 1) * 16;

    for (int t = 0; t < T; ++t) {
        const uint32_t st = base + (uint32_t)(t & 1) * STAGE_BYTES;

        if (t + 1 < T) {
            const uint32_t stn = base + (uint32_t)((t + 1) & 1) * STAGE_BYTES;
            load_stage(stn, srcA(t + 1, g_ah), srcA(t + 1, g_al),
                       srcW(t + 1, g_wth), srcW(t + 1, g_wtl), tid);
            CP_COMMIT();
            CP_WAIT(1);
        } else {
            CP_WAIT(0);
        }
        __syncthreads();

#pragma unroll
        for (int ks = 0; ks < KT / 16; ++ks) {
            const int kb = ks * 32;
            uint32_t ah[2][4], al[2][4], wh[4][4], wl[4][4];
#pragma unroll
            for (int i = 0; i < 2; ++i) {
                uint32_t ad = st + SWZ((arow + i * 16) * 128 + kb + acol);
                ldsm4(ah[i], ad);
                ldsm4(al[i], ad + OFF_AL);
            }
#pragma unroll
            for (int j = 0; j < 4; ++j) {
                uint32_t wd = st + OFF_WH + SWZ((wrow + j * 16) * 128 + kb + wcol);
                ldsm4(wh[j], wd);
                ldsm4(wl[j], wd + (OFF_WL - OFF_WH));
            }
#pragma unroll
            for (int i = 0; i < 2; ++i)
#pragma unroll
                for (int j = 0; j < 4; ++j)
#pragma unroll
                    for (int s = 0; s < 2; ++s) {
                        float* c = acc[i][j * 2 + s];
                        mma16816(c, ah[i], wh[j][s * 2], wh[j][s * 2 + 1]);
                        mma16816(c, al[i], wh[j][s * 2], wh[j][s * 2 + 1]);
                        mma16816(c, ah[i], wl[j][s * 2], wl[j][s * 2 + 1]);
                    }
        }
        __syncthreads();
    }

    // epilogue: out[b0+.., M, ..] written exactly once
#pragma unroll
    for (int i = 0; i < 2; ++i) {
        const int m0 = b0 + wm * 32 + i * 16 + (lane >> 2);
#pragma unroll
        for (int j = 0; j < 8; ++j) {
            const int n = wn * 64 + j * 8 + (lane & 3) * 2;
            float* p0 = out + ((size_t)m0 * NORD + M) * CO + n;
            float* p1 = out + ((size_t)(m0 + 8) * NORD + M) * CO + n;
            *(float2*)p0 = make_float2(acc[i][j][0], acc[i][j][1]);
            *(float2*)p1 = make_float2(acc[i][j][2], acc[i][j][3]);
        }
    }
}

// ---------------------------------------------------------------------------
// Inputs: x, sh, weight, CG_vals, M1, M2, seg1, l_ind, seg2, num_orders_out
// ---------------------------------------------------------------------------
extern "C" void kernel_launch(void* const* d_in, const int* in_sizes, int n_in,
                              void* d_out, int out_size) {
    const float* x      = (const float*)d_in[0];
    const float* sh     = (const float*)d_in[1];
    const float* weight = (const float*)d_in[2];
    const float* CG     = (const float*)d_in[3];
    const int*   M1     = (const int*)d_in[4];
    const int*   M2     = (const int*)d_in[5];
    const int*   seg1   = (const int*)d_in[6];
    const int*   l_ind  = (const int*)d_in[7];
    const int*   seg2   = (const int*)d_in[8];
    float*       out    = (float*)d_out;

    const int nnz = in_sizes[4];
    const int G   = in_sizes[7];
    const int Bn  = in_sizes[1] / NORD;
    const int n_w = in_sizes[2] / (CI * CO);

    static bool attr_set = false;
    if (!attr_set) {
        cudaFuncSetAttribute(so3_mma, cudaFuncAttributeMaxDynamicSharedMemorySize, SMEM_DYN);
        attr_set = true;
    }

    setup_offsets<<<1, 256>>>(seg1, seg2, nnz, G);
    {
        dim3 grid(CO / 32, CI / 32, n_w);
        wsplit<<<grid, 256>>>(weight);
    }
    build_inter<<<Bn, 256>>>(x, sh, CG, M1, M2, nnz, G, Bn);
    {
        dim3 grid(Bn / 64, NORD);
        so3_mma<<<grid, 256, SMEM_DYN>>>(l_ind, out, Bn);
    }
}

// round 4
// speedup vs baseline: 3.4101x; 1.6239x over previous
#include <cuda_runtime.h>
#include <cuda_bf16.h>
#include <cstdint>

// ---------------------------------------------------------------------------
// SO3Linear (L=3, B=1024, C=256) via bf16 split-precision mma.sync GEMM.
//
//  K0 setup_offsets : contiguous range tables from seg1/seg2 (nondecreasing)
//  K1 wsplit        : W[w][ci][co] fp32 -> Wt{h,l}[w][co][ci] bf16
//  K2 build_inter   : inter[g][b][ci] fp32 -> A{h,l}[g][b][ci] bf16
//  K3 so3_mma       : per CTA (64 b-rows, 128 co, order M):
//                     fp32 accum of sum_g [Ah@Wh + Al@Wh + Ah@Wl]
//                     cp.async double buffer, 2 CTAs/SM resident.
// ---------------------------------------------------------------------------

#define NORD     16
#define CI       256
#define CO       256
#define G_MAX    156
#define NNZ_MAX  512
#define NW_MAX   40
#define B_MAX    1024

// ---- device scratch ----
__device__ __nv_bfloat16 g_ah[(size_t)G_MAX * B_MAX * CI];
__device__ __nv_bfloat16 g_al[(size_t)G_MAX * B_MAX * CI];
__device__ __nv_bfloat16 g_wth[(size_t)NW_MAX * CO * CI];
__device__ __nv_bfloat16 g_wtl[(size_t)NW_MAX * CO * CI];
__device__ int g_gs[G_MAX + 1];
__device__ int g_mg[NORD + 1];

#define SWZ(o) ((o) ^ (((o) >> 3) & 0x70))

__device__ __forceinline__ uint32_t smem_u32(const void* p) {
    uint32_t a;
    asm("{ .reg .u64 t; cvta.to.shared.u64 t, %1; cvt.u32.u64 %0, t; }" : "=r"(a) : "l"(p));
    return a;
}
__device__ __forceinline__ void cp16(uint32_t dst, const void* src) {
    asm volatile("cp.async.cg.shared.global [%0], [%1], 16;" :: "r"(dst), "l"(src) : "memory");
}
#define CP_COMMIT()  asm volatile("cp.async.commit_group;" ::: "memory")
#define CP_WAIT(N)   asm volatile("cp.async.wait_group %0;" :: "n"(N) : "memory")

__device__ __forceinline__ void ldsm4(uint32_t r[4], uint32_t addr) {
    asm volatile("ldmatrix.sync.aligned.m8n8.x4.shared.b16 {%0,%1,%2,%3}, [%4];"
                 : "=r"(r[0]), "=r"(r[1]), "=r"(r[2]), "=r"(r[3]) : "r"(addr));
}
__device__ __forceinline__ void mma16816(float c[4], const uint32_t a[4],
                                         uint32_t b0, uint32_t b1) {
    asm volatile(
        "mma.sync.aligned.m16n8k16.row.col.f32.bf16.bf16.f32 "
        "{%0,%1,%2,%3}, {%4,%5,%6,%7}, {%8,%9}, {%0,%1,%2,%3};"
        : "+f"(c[0]), "+f"(c[1]), "+f"(c[2]), "+f"(c[3])
        : "r"(a[0]), "r"(a[1]), "r"(a[2]), "r"(a[3]), "r"(b0), "r"(b1));
}

// ---------------------------------------------------------------------------
// K0: range tables
// ---------------------------------------------------------------------------
__global__ void setup_offsets(const int* __restrict__ seg1,
                              const int* __restrict__ seg2,
                              int nnz, int G) {
    int tid = threadIdx.x;
    for (int i = tid; i < nnz; i += blockDim.x) {
        if (i == 0) g_gs[seg1[0]] = 0;
        else if (seg1[i] != seg1[i - 1]) g_gs[seg1[i]] = i;
    }
    for (int i = tid; i < G; i += blockDim.x) {
        if (i == 0) g_mg[seg2[0]] = 0;
        else if (seg2[i] != seg2[i - 1]) g_mg[seg2[i]] = i;
    }
    if (tid == 0) { g_gs[G] = nnz; g_mg[NORD] = G; }
}

// ---------------------------------------------------------------------------
// K1: transpose + split weights: W[w][ci][co] -> Wt{h,l}[w][co][ci]
// ---------------------------------------------------------------------------
__global__ __launch_bounds__(256) void wsplit(const float* __restrict__ weight) {
    __shared__ float tile[32][33];
    const int w  = blockIdx.z;
    const int bx = blockIdx.x;
    const int by = blockIdx.y;
    const int tx = threadIdx.x & 31;
    const int ty = threadIdx.x >> 5;

    const float* in = weight + (size_t)w * CI * CO;
#pragma unroll
    for (int j = 0; j < 4; ++j) {
        int r = ty + 8 * j;
        tile[r][tx] = in[(size_t)(by * 32 + r) * CO + bx * 32 + tx];
    }
    __syncthreads();
#pragma unroll
    for (int j = 0; j < 4; ++j) {
        int r = ty + 8 * j;
        float v = tile[tx][r];
        __nv_bfloat16 h = __float2bfloat16(v);
        float lo = v - __bfloat162float(h);
        size_t o = ((size_t)w * CO + (bx * 32 + r)) * CI + by * 32 + tx;
        g_wth[o] = h;
        g_wtl[o] = __float2bfloat16(lo);
    }
}

// ---------------------------------------------------------------------------
// K2: build inter, split into bf16 hi/lo planes. One block per b.
// ---------------------------------------------------------------------------
__global__ __launch_bounds__(256) void build_inter(
    const float* __restrict__ x,
    const float* __restrict__ sh,
    const float* __restrict__ CG,
    const int* __restrict__ M1,
    const int* __restrict__ M2,
    int nnz, int G, int Bn) {

    __shared__ float coefs[NNZ_MAX];
    __shared__ int   m1s[NNZ_MAX];
    __shared__ int   gs_s[G_MAX + 1];

    const int b   = blockIdx.x;
    const int tid = threadIdx.x;

    for (int i = tid; i < nnz; i += blockDim.x) {
        coefs[i] = CG[i] * sh[b * NORD + M2[i]];
        m1s[i]   = M1[i];
    }
    for (int i = tid; i <= G; i += blockDim.x) gs_s[i] = g_gs[i];
    __syncthreads();

    const float* xb = x + (size_t)b * NORD * CI;
    const int ci = tid;

    for (int g = 0; g < G; ++g) {
        float acc = 0.f;
        const int e = gs_s[g + 1];
        for (int idx = gs_s[g]; idx < e; ++idx)
            acc = fmaf(coefs[idx], xb[m1s[idx] * CI + ci], acc);
        __nv_bfloat16 h = __float2bfloat16(acc);
        float lo = acc - __bfloat162float(h);
        size_t o = ((size_t)g * Bn + b) * CI + ci;
        g_ah[o] = h;
        g_al[o] = __float2bfloat16(lo);
    }
}

// ---------------------------------------------------------------------------
// K3: mma.sync GEMM. Grid (Bn/64, CO/128, NORD), 256 threads (4m x 2n warps).
// Block tile: 64(b) x 128(co), K-tile 64.
// Stage 48KB: Ah 8K | Al 8K | Wh 16K | Wl 16K. Double buffered -> 96KB dyn,
// 2 CTAs resident per SM.
// ---------------------------------------------------------------------------
#define KT          64
#define OFF_AL      8192
#define OFF_WH      16384
#define OFF_WL      32768
#define STAGE_BYTES 49152
#define SMEM_DYN    (2 * STAGE_BYTES + 1024)

__device__ __forceinline__ void load_stage(uint32_t st,
                                           const char* gAh, const char* gAl,
                                           const char* gWh, const char* gWl,
                                           int tid) {
#pragma unroll
    for (int i = 0; i < 2; ++i) {           // A planes: 64 rows x 8 chunks
        int idx = tid + i * 256;
        int r = idx >> 3, c = idx & 7;
        uint32_t so = SWZ(r * 128 + c * 16);
        size_t go = (size_t)r * (CI * 2) + c * 16;
        cp16(st + so,          gAh + go);
        cp16(st + OFF_AL + so, gAl + go);
    }
#pragma unroll
    for (int i = 0; i < 4; ++i) {           // W planes: 128 rows x 8 chunks
        int idx = tid + i * 256;
        int r = idx >> 3, c = idx & 7;
        uint32_t so = SWZ(r * 128 + c * 16);
        size_t go = (size_t)r * (CI * 2) + c * 16;
        cp16(st + OFF_WH + so, gWh + go);
        cp16(st + OFF_WL + so, gWl + go);
    }
}

__global__ __launch_bounds__(256, 2) void so3_mma(
    const int* __restrict__ l_ind,
    float* __restrict__ out,
    int Bn) {

    extern __shared__ char smem[];
    const uint32_t sb   = smem_u32(smem);
    const uint32_t base = (sb + 1023) & ~1023u;

    const int tid  = threadIdx.x;
    const int wid  = tid >> 5;
    const int lane = tid & 31;
    const int wm   = wid & 3;          // 4 m-warps (16 rows each)
    const int wn   = wid >> 2;         // 2 n-warps (64 cols each)

    const int b0  = blockIdx.x * 64;
    const int cob = blockIdx.y * 128;
    const int M   = blockIdx.z;
    const int gbeg = g_mg[M];
    const int gend = g_mg[M + 1];
    const int T = (gend - gbeg) * (CI / KT);   // k-tiles

    float acc[8][4];
#pragma unroll
    for (int j = 0; j < 8; ++j)
#pragma unroll
        for (int q = 0; q < 4; ++q) acc[j][q] = 0.f;

    auto srcA = [&](int t, const __nv_bfloat16* plane) -> const char* {
        int g = gbeg + (t >> 2), kc = t & 3;
        return (const char*)plane + (((size_t)g * Bn + b0) * CI + kc * KT) * 2;
    };
    auto srcW = [&](int t, const __nv_bfloat16* plane) -> const char* {
        int g = gbeg + (t >> 2), kc = t & 3;
        int w = __ldg(l_ind + g);
        return (const char*)plane + (((size_t)w * CO + cob) * CI + kc * KT) * 2;
    };

    // prologue
    load_stage(base, srcA(0, g_ah), srcA(0, g_al), srcW(0, g_wth), srcW(0, g_wtl), tid);
    CP_COMMIT();

    // ldmatrix lane addressing (fixed per thread)
    const int arow = wm * 16 + (lane & 15);
    const int acol = (lane >> 4) * 16;
    const int wrow = wn * 64 + (lane & 7) + ((lane >> 4) << 3);
    const int wcol = ((lane >> 3) & 1) * 16;

    for (int t = 0; t < T; ++t) {
        const uint32_t st = base + (uint32_t)(t & 1) * STAGE_BYTES;

        if (t + 1 < T) {
            const uint32_t stn = base + (uint32_t)((t + 1) & 1) * STAGE_BYTES;
            load_stage(stn, srcA(t + 1, g_ah), srcA(t + 1, g_al),
                       srcW(t + 1, g_wth), srcW(t + 1, g_wtl), tid);
            CP_COMMIT();
            CP_WAIT(1);
        } else {
            CP_WAIT(0);
        }
        __syncthreads();

#pragma unroll
        for (int ks = 0; ks < KT / 16; ++ks) {
            const int kb = ks * 32;
            uint32_t ah[4], al[4];
            {
                uint32_t ad = st + SWZ(arow * 128 + kb + acol);
                ldsm4(ah, ad);
                ldsm4(al, ad + OFF_AL);
            }
#pragma unroll
            for (int j = 0; j < 4; ++j) {
                uint32_t whf[4], wlf[4];
                uint32_t wd = st + OFF_WH + SWZ((wrow + j * 16) * 128 + kb + wcol);
                ldsm4(whf, wd);
                ldsm4(wlf, wd + (OFF_WL - OFF_WH));
#pragma unroll
                for (int s = 0; s < 2; ++s) {
                    float* c = acc[j * 2 + s];
                    mma16816(c, ah, whf[s * 2], whf[s * 2 + 1]);
                    mma16816(c, al, whf[s * 2], whf[s * 2 + 1]);
                    mma16816(c, ah, wlf[s * 2], wlf[s * 2 + 1]);
                }
            }
        }
        __syncthreads();
    }

    // epilogue: out[b0+.., M, cob+..] written exactly once
    const int m0 = b0 + wm * 16 + (lane >> 2);
#pragma unroll
    for (int j = 0; j < 8; ++j) {
        const int n = cob + wn * 64 + j * 8 + (lane & 3) * 2;
        float* p0 = out + ((size_t)m0 * NORD + M) * CO + n;
        float* p1 = out + ((size_t)(m0 + 8) * NORD + M) * CO + n;
        *(float2*)p0 = make_float2(acc[j][0], acc[j][1]);
        *(float2*)p1 = make_float2(acc[j][2], acc[j][3]);
    }
}

// ---------------------------------------------------------------------------
// Inputs: x, sh, weight, CG_vals, M1, M2, seg1, l_ind, seg2, num_orders_out
// ---------------------------------------------------------------------------
extern "C" void kernel_launch(void* const* d_in, const int* in_sizes, int n_in,
                              void* d_out, int out_size) {
    const float* x      = (const float*)d_in[0];
    const float* sh     = (const float*)d_in[1];
    const float* weight = (const float*)d_in[2];
    const float* CG     = (const float*)d_in[3];
    const int*   M1     = (const int*)d_in[4];
    const int*   M2     = (const int*)d_in[5];
    const int*   seg1   = (const int*)d_in[6];
    const int*   l_ind  = (const int*)d_in[7];
    const int*   seg2   = (const int*)d_in[8];
    float*       out    = (float*)d_out;

    const int nnz = in_sizes[4];
    const int G   = in_sizes[7];
    const int Bn  = in_sizes[1] / NORD;
    const int n_w = in_sizes[2] / (CI * CO);

    static bool attr_set = false;
    if (!attr_set) {
        cudaFuncSetAttribute(so3_mma, cudaFuncAttributeMaxDynamicSharedMemorySize, SMEM_DYN);
        attr_set = true;
    }

    setup_offsets<<<1, 256>>>(seg1, seg2, nnz, G);
    {
        dim3 grid(CO / 32, CI / 32, n_w);
        wsplit<<<grid, 256>>>(weight);
    }
    build_inter<<<Bn, 256>>>(x, sh, CG, M1, M2, nnz, G, Bn);
    {
        dim3 grid(Bn / 64, CO / 128, NORD);
        so3_mma<<<grid, 256, SMEM_DYN>>>(l_ind, out, Bn);
    }
}

// round 5
// speedup vs baseline: 3.7643x; 1.1039x over previous
#include <cuda_runtime.h>
#include <cuda_bf16.h>
#include <cstdint>

// ---------------------------------------------------------------------------
// SO3Linear (L=3, B=1024, C=256) via bf16 split-precision mma.sync GEMM.
//
//  K0 setup_offsets : contiguous range tables from seg1/seg2 (nondecreasing)
//  K1 wsplit        : W[w][ci][co] fp32 -> Wt{h,l}[w][co][ci] bf16
//  K2 build_inter   : inter[g][b][ci] fp32 -> A{h,l}[g][b][ci] bf16 (float4 vec)
//  K3 so3_mma       : per CTA (128 b-rows, 128 co, order M):
//                     fp32 accum of sum_g [Ah@Wh + Al@Wh + Ah@Wl]
//                     KT=32, 3-stage cp.async, 2 CTAs/SM.
//                     SMEM row layout: [hi 32k | lo 32k] = 128B, SW128.
// ---------------------------------------------------------------------------

#define NORD     16
#define CI       256
#define CO       256
#define G_MAX    156
#define NNZ_MAX  512
#define NW_MAX   40
#define B_MAX    1024

// ---- device scratch ----
__device__ __nv_bfloat16 g_ah[(size_t)G_MAX * B_MAX * CI];
__device__ __nv_bfloat16 g_al[(size_t)G_MAX * B_MAX * CI];
__device__ __nv_bfloat16 g_wth[(size_t)NW_MAX * CO * CI];
__device__ __nv_bfloat16 g_wtl[(size_t)NW_MAX * CO * CI];
__device__ int g_gs[G_MAX + 1];
__device__ int g_mg[NORD + 1];

#define SWZ(o) ((o) ^ (((o) >> 3) & 0x70))

__device__ __forceinline__ uint32_t smem_u32(const void* p) {
    uint32_t a;
    asm("{ .reg .u64 t; cvta.to.shared.u64 t, %1; cvt.u32.u64 %0, t; }" : "=r"(a) : "l"(p));
    return a;
}
__device__ __forceinline__ void cp16(uint32_t dst, const void* src) {
    asm volatile("cp.async.cg.shared.global [%0], [%1], 16;" :: "r"(dst), "l"(src) : "memory");
}
#define CP_COMMIT()  asm volatile("cp.async.commit_group;" ::: "memory")
#define CP_WAIT(N)   asm volatile("cp.async.wait_group %0;" :: "n"(N) : "memory")

__device__ __forceinline__ void ldsm4(uint32_t r[4], uint32_t addr) {
    asm volatile("ldmatrix.sync.aligned.m8n8.x4.shared.b16 {%0,%1,%2,%3}, [%4];"
                 : "=r"(r[0]), "=r"(r[1]), "=r"(r[2]), "=r"(r[3]) : "r"(addr));
}
__device__ __forceinline__ void mma16816(float c[4], const uint32_t a[4],
                                         uint32_t b0, uint32_t b1) {
    asm volatile(
        "mma.sync.aligned.m16n8k16.row.col.f32.bf16.bf16.f32 "
        "{%0,%1,%2,%3}, {%4,%5,%6,%7}, {%8,%9}, {%0,%1,%2,%3};"
        : "+f"(c[0]), "+f"(c[1]), "+f"(c[2]), "+f"(c[3])
        : "r"(a[0]), "r"(a[1]), "r"(a[2]), "r"(a[3]), "r"(b0), "r"(b1));
}

// ---------------------------------------------------------------------------
// K0: range tables
// ---------------------------------------------------------------------------
__global__ void setup_offsets(const int* __restrict__ seg1,
                              const int* __restrict__ seg2,
                              int nnz, int G) {
    int tid = threadIdx.x;
    for (int i = tid; i < nnz; i += blockDim.x) {
        if (i == 0) g_gs[seg1[0]] = 0;
        else if (seg1[i] != seg1[i - 1]) g_gs[seg1[i]] = i;
    }
    for (int i = tid; i < G; i += blockDim.x) {
        if (i == 0) g_mg[seg2[0]] = 0;
        else if (seg2[i] != seg2[i - 1]) g_mg[seg2[i]] = i;
    }
    if (tid == 0) { g_gs[G] = nnz; g_mg[NORD] = G; }
}

// ---------------------------------------------------------------------------
// K1: transpose + split weights: W[w][ci][co] -> Wt{h,l}[w][co][ci]
// ---------------------------------------------------------------------------
__global__ __launch_bounds__(256) void wsplit(const float* __restrict__ weight) {
    __shared__ float tile[32][33];
    const int w  = blockIdx.z;
    const int bx = blockIdx.x;
    const int by = blockIdx.y;
    const int tx = threadIdx.x & 31;
    const int ty = threadIdx.x >> 5;

    const float* in = weight + (size_t)w * CI * CO;
#pragma unroll
    for (int j = 0; j < 4; ++j) {
        int r = ty + 8 * j;
        tile[r][tx] = in[(size_t)(by * 32 + r) * CO + bx * 32 + tx];
    }
    __syncthreads();
#pragma unroll
    for (int j = 0; j < 4; ++j) {
        int r = ty + 8 * j;
        float v = tile[tx][r];
        __nv_bfloat16 h = __float2bfloat16(v);
        float lo = v - __bfloat162float(h);
        size_t o = ((size_t)w * CO + (bx * 32 + r)) * CI + by * 32 + tx;
        g_wth[o] = h;
        g_wtl[o] = __float2bfloat16(lo);
    }
}

// ---------------------------------------------------------------------------
// K2: build inter (vectorized). Block = 4 b values; thread owns 4 ci (float4).
// ---------------------------------------------------------------------------
__global__ __launch_bounds__(256) void build_inter(
    const float* __restrict__ x,
    const float* __restrict__ sh,
    const float* __restrict__ CG,
    const int* __restrict__ M1,
    const int* __restrict__ M2,
    int nnz, int G, int Bn) {

    __shared__ float coefs4[4][NNZ_MAX];
    __shared__ int   m1s[NNZ_MAX];
    __shared__ int   gs_s[G_MAX + 1];

    const int b_base = blockIdx.x * 4;
    const int tid    = threadIdx.x;
    const int bsub   = tid >> 6;          // 0..3
    const int c4     = (tid & 63) * 4;    // ci base

    for (int i = tid; i < nnz; i += 256) m1s[i] = M1[i] * CI;
#pragma unroll
    for (int bb = 0; bb < 4; ++bb) {
        const float* shb = sh + (size_t)(b_base + bb) * NORD;
        for (int i = tid; i < nnz; i += 256)
            coefs4[bb][i] = CG[i] * shb[M2[i]];
    }
    for (int i = tid; i <= G; i += 256) gs_s[i] = g_gs[i];
    __syncthreads();

    const int b = b_base + bsub;
    const float* xb = x + (size_t)b * NORD * CI + c4;
    const float* cf = coefs4[bsub];

    for (int g = 0; g < G; ++g) {
        float ax = 0.f, ay = 0.f, az = 0.f, aw = 0.f;
        const int e = gs_s[g + 1];
        for (int idx = gs_s[g]; idx < e; ++idx) {
            const float c = cf[idx];
            const float4 xv = *reinterpret_cast<const float4*>(xb + m1s[idx]);
            ax = fmaf(c, xv.x, ax);
            ay = fmaf(c, xv.y, ay);
            az = fmaf(c, xv.z, az);
            aw = fmaf(c, xv.w, aw);
        }
        __nv_bfloat162 h01 = __floats2bfloat162_rn(ax, ay);
        __nv_bfloat162 h23 = __floats2bfloat162_rn(az, aw);
        float lx = ax - __bfloat162float(__low2bfloat16(h01));
        float ly = ay - __bfloat162float(__high2bfloat16(h01));
        float lz = az - __bfloat162float(__low2bfloat16(h23));
        float lw = aw - __bfloat162float(__high2bfloat16(h23));
        __nv_bfloat162 l01 = __floats2bfloat162_rn(lx, ly);
        __nv_bfloat162 l23 = __floats2bfloat162_rn(lz, lw);

        const size_t o = ((size_t)g * Bn + b) * CI + c4;
        *reinterpret_cast<uint2*>(g_ah + o) =
            make_uint2(*(uint32_t*)&h01, *(uint32_t*)&h23);
        *reinterpret_cast<uint2*>(g_al + o) =
            make_uint2(*(uint32_t*)&l01, *(uint32_t*)&l23);
    }
}

// ---------------------------------------------------------------------------
// K3: mma.sync GEMM. Grid (Bn/128, CO/128, NORD), 256 threads (4m x 2n warps).
// Block tile: 128(b) x 128(co), KT=32. Stage 32KB: A 16K | W 16K.
// SMEM row (128B, SW128): [hi 32k (64B) | lo 32k (64B)].
// 3 stages = 96KB dyn -> 2 CTAs/SM.
// ---------------------------------------------------------------------------
#define KT          32
#define OFF_W       16384
#define STAGE_BYTES 32768
#define SMEM_DYN    (3 * STAGE_BYTES + 1024)

__device__ __forceinline__ void load_stage(uint32_t st,
                                           const char* gAh, const char* gAl,
                                           const char* gWh, const char* gWl,
                                           int tid) {
    // A: 128 rows x 8 chunks (c<4: hi, c>=4: lo)
#pragma unroll
    for (int i = 0; i < 4; ++i) {
        int idx = tid + i * 256;
        int r = idx >> 3, c = idx & 7;
        uint32_t so = SWZ(r * 128 + c * 16);
        const char* src = (c < 4) ? (gAh + (size_t)r * (CI * 2) + c * 16)
                                  : (gAl + (size_t)r * (CI * 2) + (c - 4) * 16);
        cp16(st + so, src);
    }
    // W: 128 rows x 8 chunks
#pragma unroll
    for (int i = 0; i < 4; ++i) {
        int idx = tid + i * 256;
        int r = idx >> 3, c = idx & 7;
        uint32_t so = SWZ(r * 128 + c * 16);
        const char* src = (c < 4) ? (gWh + (size_t)r * (CI * 2) + c * 16)
                                  : (gWl + (size_t)r * (CI * 2) + (c - 4) * 16);
        cp16(st + OFF_W + so, src);
    }
}

__global__ __launch_bounds__(256, 2) void so3_mma(
    const int* __restrict__ l_ind,
    float* __restrict__ out,
    int Bn) {

    extern __shared__ char smem[];
    const uint32_t sb   = smem_u32(smem);
    const uint32_t base = (sb + 1023) & ~1023u;

    const int tid  = threadIdx.x;
    const int wid  = tid >> 5;
    const int lane = tid & 31;
    const int wm   = wid & 3;          // 4 m-warps (32 rows each)
    const int wn   = wid >> 2;         // 2 n-warps (64 cols each)

    const int b0  = blockIdx.x * 128;
    const int cob = blockIdx.y * 128;
    const int M   = blockIdx.z;
    const int gbeg = g_mg[M];
    const int gend = g_mg[M + 1];
    const int T = (gend - gbeg) * (CI / KT);   // stages (8 per group)

    float acc[2][8][4];
#pragma unroll
    for (int i = 0; i < 2; ++i)
#pragma unroll
        for (int j = 0; j < 8; ++j)
#pragma unroll
            for (int q = 0; q < 4; ++q) acc[i][j][q] = 0.f;

    auto srcA = [&](int t, const __nv_bfloat16* plane) -> const char* {
        int g = gbeg + (t >> 3), kc = t & 7;
        return (const char*)plane + (((size_t)g * Bn + b0) * CI + kc * KT) * 2;
    };
    auto srcW = [&](int t, const __nv_bfloat16* plane) -> const char* {
        int g = gbeg + (t >> 3), kc = t & 7;
        int w = __ldg(l_ind + g);
        return (const char*)plane + (((size_t)w * CO + cob) * CI + kc * KT) * 2;
    };

    // prologue: 2 stages in flight
    load_stage(base, srcA(0, g_ah), srcA(0, g_al), srcW(0, g_wth), srcW(0, g_wtl), tid);
    CP_COMMIT();
    if (T > 1) {
        load_stage(base + STAGE_BYTES, srcA(1, g_ah), srcA(1, g_al),
                   srcW(1, g_wth), srcW(1, g_wtl), tid);
        CP_COMMIT();
    }

    // ldmatrix lane addressing
    const int arow = wm * 32 + (lane & 15);
    const int acol = (lane >> 4) * 16;                       // 0/16
    const int wrow = wn * 64 + (lane & 7) + ((lane >> 4) << 3);
    const int wcol = ((lane >> 3) & 1) * 16;                 // 0/16

    int stage = 0;
    for (int t = 0; t < T; ++t) {
        const uint32_t st = base + (uint32_t)stage * STAGE_BYTES;
        stage = (stage + 1 == 3) ? 0 : stage + 1;

        if (t + 2 < T) {
            const int s2 = (stage + 1 == 3) ? 0 : stage + 1;
            load_stage(base + (uint32_t)s2 * STAGE_BYTES,
                       srcA(t + 2, g_ah), srcA(t + 2, g_al),
                       srcW(t + 2, g_wth), srcW(t + 2, g_wtl), tid);
            CP_COMMIT();
            CP_WAIT(2);
        } else if (t + 1 < T) {
            CP_WAIT(1);
        } else {
            CP_WAIT(0);
        }
        __syncthreads();

#pragma unroll
        for (int ks = 0; ks < 2; ++ks) {           // two k16 steps in KT=32
            const int kb = ks * 32;                // byte offset within hi half
            uint32_t ah[2][4], al[2][4];
#pragma unroll
            for (int i = 0; i < 2; ++i) {
                uint32_t ad = st + SWZ((arow + i * 16) * 128 + kb + acol);
                ldsm4(ah[i], ad);
                ldsm4(al[i], ad ^ 64);             // lo half of the row
            }
#pragma unroll
            for (int j = 0; j < 4; ++j) {
                uint32_t whf[4], wlf[4];
                uint32_t wd = st + OFF_W + SWZ((wrow + j * 16) * 128 + kb + wcol);
                ldsm4(whf, wd);
                ldsm4(wlf, wd ^ 64);
#pragma unroll
                for (int i = 0; i < 2; ++i)
#pragma unroll
                    for (int s = 0; s < 2; ++s) {
                        float* c = acc[i][j * 2 + s];
                        mma16816(c, ah[i], whf[s * 2], whf[s * 2 + 1]);
                        mma16816(c, al[i], whf[s * 2], whf[s * 2 + 1]);
                        mma16816(c, ah[i], wlf[s * 2], wlf[s * 2 + 1]);
                    }
            }
        }
        __syncthreads();
    }

    // epilogue: out[b0+.., M, cob+..] exactly once
#pragma unroll
    for (int i = 0; i < 2; ++i) {
        const int m0 = b0 + wm * 32 + i * 16 + (lane >> 2);
#pragma unroll
        for (int j = 0; j < 8; ++j) {
            const int n = cob + wn * 64 + j * 8 + (lane & 3) * 2;
            float* p0 = out + ((size_t)m0 * NORD + M) * CO + n;
            float* p1 = out + ((size_t)(m0 + 8) * NORD + M) * CO + n;
            *(float2*)p0 = make_float2(acc[i][j][0], acc[i][j][1]);
            *(float2*)p1 = make_float2(acc[i][j][2], acc[i][j][3]);
        }
    }
}

// ---------------------------------------------------------------------------
// Inputs: x, sh, weight, CG_vals, M1, M2, seg1, l_ind, seg2, num_orders_out
// ---------------------------------------------------------------------------
extern "C" void kernel_launch(void* const* d_in, const int* in_sizes, int n_in,
                              void* d_out, int out_size) {
    const float* x      = (const float*)d_in[0];
    const float* sh     = (const float*)d_in[1];
    const float* weight = (const float*)d_in[2];
    const float* CG     = (const float*)d_in[3];
    const int*   M1     = (const int*)d_in[4];
    const int*   M2     = (const int*)d_in[5];
    const int*   seg1   = (const int*)d_in[6];
    const int*   l_ind  = (const int*)d_in[7];
    const int*   seg2   = (const int*)d_in[8];
    float*       out    = (float*)d_out;

    const int nnz = in_sizes[4];
    const int G   = in_sizes[7];
    const int Bn  = in_sizes[1] / NORD;
    const int n_w = in_sizes[2] / (CI * CO);

    static bool attr_set = false;
    if (!attr_set) {
        cudaFuncSetAttribute(so3_mma, cudaFuncAttributeMaxDynamicSharedMemorySize, SMEM_DYN);
        attr_set = true;
    }

    setup_offsets<<<1, 256>>>(seg1, seg2, nnz, G);
    {
        dim3 grid(CO / 32, CI / 32, n_w);
        wsplit<<<grid, 256>>>(weight);
    }
    build_inter<<<Bn / 4, 256>>>(x, sh, CG, M1, M2, nnz, G, Bn);
    {
        dim3 grid(Bn / 128, CO / 128, NORD);
        so3_mma<<<grid, 256, SMEM_DYN>>>(l_ind, out, Bn);
    }
}

// round 6
// speedup vs baseline: 4.6456x; 1.2341x over previous
#include <cuda_runtime.h>
#include <cuda_bf16.h>
#include <cstdint>

// ---------------------------------------------------------------------------
// SO3Linear (L=3, B=1024, C=256) via bf16 split-precision mma.sync GEMM.
//
//  K0 setup_offsets : contiguous range tables from seg1/seg2 (nondecreasing)
//  K1 wsplit        : W[w][ci][co] fp32 -> Wt{h,l}[w][co][ci] bf16
//  K2 build_inter   : inter[g][b][ci] fp32 -> A{h,l}[g][b][ci] bf16
//                     (float4 vec, group-range split x4 for parallelism)
//  K3 so3_mma       : per CTA (64 b-rows, 128 co, order M):
//                     fp32 accum of sum_g [Ah@Wh + Al@Wh + Ah@Wl]
//                     KT=64, 2-stage cp.async, 2 CTAs/SM (R4 geometry),
//                     heavy-M-first z remap for tail balance.
// ---------------------------------------------------------------------------

#define NORD     16
#define CI       256
#define CO       256
#define G_MAX    156
#define NNZ_MAX  512
#define NW_MAX   40
#define B_MAX    1024

// ---- device scratch ----
__device__ __nv_bfloat16 g_ah[(size_t)G_MAX * B_MAX * CI];
__device__ __nv_bfloat16 g_al[(size_t)G_MAX * B_MAX * CI];
__device__ __nv_bfloat16 g_wth[(size_t)NW_MAX * CO * CI];
__device__ __nv_bfloat16 g_wtl[(size_t)NW_MAX * CO * CI];
__device__ int g_gs[G_MAX + 1];
__device__ int g_mg[NORD + 1];

// heavy-orders-first schedule (groups/M: l=2 ->11, l=3 ->10, l=1 ->9, l=0 ->4)
__constant__ int c_morder[NORD] = {4,5,6,7,8, 9,10,11,12,13,14,15, 1,2,3, 0};

#define SWZ(o) ((o) ^ (((o) >> 3) & 0x70))

__device__ __forceinline__ uint32_t smem_u32(const void* p) {
    uint32_t a;
    asm("{ .reg .u64 t; cvta.to.shared.u64 t, %1; cvt.u32.u64 %0, t; }" : "=r"(a) : "l"(p));
    return a;
}
__device__ __forceinline__ void cp16(uint32_t dst, const void* src) {
    asm volatile("cp.async.cg.shared.global [%0], [%1], 16;" :: "r"(dst), "l"(src) : "memory");
}
#define CP_COMMIT()  asm volatile("cp.async.commit_group;" ::: "memory")
#define CP_WAIT(N)   asm volatile("cp.async.wait_group %0;" :: "n"(N) : "memory")

__device__ __forceinline__ void ldsm4(uint32_t r[4], uint32_t addr) {
    asm volatile("ldmatrix.sync.aligned.m8n8.x4.shared.b16 {%0,%1,%2,%3}, [%4];"
                 : "=r"(r[0]), "=r"(r[1]), "=r"(r[2]), "=r"(r[3]) : "r"(addr));
}
__device__ __forceinline__ void mma16816(float c[4], const uint32_t a[4],
                                         uint32_t b0, uint32_t b1) {
    asm volatile(
        "mma.sync.aligned.m16n8k16.row.col.f32.bf16.bf16.f32 "
        "{%0,%1,%2,%3}, {%4,%5,%6,%7}, {%8,%9}, {%0,%1,%2,%3};"
        : "+f"(c[0]), "+f"(c[1]), "+f"(c[2]), "+f"(c[3])
        : "r"(a[0]), "r"(a[1]), "r"(a[2]), "r"(a[3]), "r"(b0), "r"(b1));
}

// ---------------------------------------------------------------------------
// K0: range tables
// ---------------------------------------------------------------------------
__global__ void setup_offsets(const int* __restrict__ seg1,
                              const int* __restrict__ seg2,
                              int nnz, int G) {
    int tid = threadIdx.x;
    for (int i = tid; i < nnz; i += blockDim.x) {
        if (i == 0) g_gs[seg1[0]] = 0;
        else if (seg1[i] != seg1[i - 1]) g_gs[seg1[i]] = i;
    }
    for (int i = tid; i < G; i += blockDim.x) {
        if (i == 0) g_mg[seg2[0]] = 0;
        else if (seg2[i] != seg2[i - 1]) g_mg[seg2[i]] = i;
    }
    if (tid == 0) { g_gs[G] = nnz; g_mg[NORD] = G; }
}

// ---------------------------------------------------------------------------
// K1: transpose + split weights: W[w][ci][co] -> Wt{h,l}[w][co][ci]
// ---------------------------------------------------------------------------
__global__ __launch_bounds__(256) void wsplit(const float* __restrict__ weight) {
    __shared__ float tile[32][33];
    const int w  = blockIdx.z;
    const int bx = blockIdx.x;
    const int by = blockIdx.y;
    const int tx = threadIdx.x & 31;
    const int ty = threadIdx.x >> 5;

    const float* in = weight + (size_t)w * CI * CO;
#pragma unroll
    for (int j = 0; j < 4; ++j) {
        int r = ty + 8 * j;
        tile[r][tx] = in[(size_t)(by * 32 + r) * CO + bx * 32 + tx];
    }
    __syncthreads();
#pragma unroll
    for (int j = 0; j < 4; ++j) {
        int r = ty + 8 * j;
        float v = tile[tx][r];
        __nv_bfloat16 h = __float2bfloat16(v);
        float lo = v - __bfloat162float(h);
        size_t o = ((size_t)w * CO + (bx * 32 + r)) * CI + by * 32 + tx;
        g_wth[o] = h;
        g_wtl[o] = __float2bfloat16(lo);
    }
}

// ---------------------------------------------------------------------------
// K2: build inter (vectorized, g-split). Grid (Bn/4, 4); block = 4 b values,
// quarter of the group range. Thread owns 4 ci (float4).
// ---------------------------------------------------------------------------
__global__ __launch_bounds__(256) void build_inter(
    const float* __restrict__ x,
    const float* __restrict__ sh,
    const float* __restrict__ CG,
    const int* __restrict__ M1,
    const int* __restrict__ M2,
    int nnz, int G, int Bn) {

    __shared__ float coefs4[4][NNZ_MAX];
    __shared__ int   m1s[NNZ_MAX];
    __shared__ int   gs_s[G_MAX + 1];

    const int b_base = blockIdx.x * 4;
    const int q      = blockIdx.y;
    const int tid    = threadIdx.x;
    const int bsub   = tid >> 6;          // 0..3
    const int c4     = (tid & 63) * 4;    // ci base

    const int gq0 = (G * q) >> 2;
    const int gq1 = (G * (q + 1)) >> 2;

    for (int i = tid; i <= G; i += 256) gs_s[i] = g_gs[i];
    __syncthreads();
    const int n0 = gs_s[gq0];
    const int n1 = gs_s[gq1];

    for (int i = n0 + tid; i < n1; i += 256) m1s[i] = M1[i] * CI;
#pragma unroll
    for (int bb = 0; bb < 4; ++bb) {
        const float* shb = sh + (size_t)(b_base + bb) * NORD;
        for (int i = n0 + tid; i < n1; i += 256)
            coefs4[bb][i] = CG[i] * shb[M2[i]];
    }
    __syncthreads();

    const int b = b_base + bsub;
    const float* xb = x + (size_t)b * NORD * CI + c4;
    const float* cf = coefs4[bsub];

    for (int g = gq0; g < gq1; ++g) {
        float ax = 0.f, ay = 0.f, az = 0.f, aw = 0.f;
        const int e = gs_s[g + 1];
        for (int idx = gs_s[g]; idx < e; ++idx) {
            const float c = cf[idx];
            const float4 xv = *reinterpret_cast<const float4*>(xb + m1s[idx]);
            ax = fmaf(c, xv.x, ax);
            ay = fmaf(c, xv.y, ay);
            az = fmaf(c, xv.z, az);
            aw = fmaf(c, xv.w, aw);
        }
        __nv_bfloat162 h01 = __floats2bfloat162_rn(ax, ay);
        __nv_bfloat162 h23 = __floats2bfloat162_rn(az, aw);
        float lx = ax - __bfloat162float(__low2bfloat16(h01));
        float ly = ay - __bfloat162float(__high2bfloat16(h01));
        float lz = az - __bfloat162float(__low2bfloat16(h23));
        float lw = aw - __bfloat162float(__high2bfloat16(h23));
        __nv_bfloat162 l01 = __floats2bfloat162_rn(lx, ly);
        __nv_bfloat162 l23 = __floats2bfloat162_rn(lz, lw);

        const size_t o = ((size_t)g * Bn + b) * CI + c4;
        *reinterpret_cast<uint2*>(g_ah + o) =
            make_uint2(*(uint32_t*)&h01, *(uint32_t*)&h23);
        *reinterpret_cast<uint2*>(g_al + o) =
            make_uint2(*(uint32_t*)&l01, *(uint32_t*)&l23);
    }
}

// ---------------------------------------------------------------------------
// K3: mma.sync GEMM (R4 geometry). Grid (Bn/64, CO/128, NORD),
// 256 threads (4m x 2n warps). Block tile 64(b) x 128(co), KT=64.
// Stage 48KB: Ah 8K | Al 8K | Wh 16K | Wl 16K. Double buffered -> 96KB dyn,
// 2 CTAs/SM. M remapped heavy-first via c_morder.
// ---------------------------------------------------------------------------
#define KT          64
#define OFF_AL      8192
#define OFF_WH      16384
#define OFF_WL      32768
#define STAGE_BYTES 49152
#define SMEM_DYN    (2 * STAGE_BYTES + 1024)

__device__ __forceinline__ void load_stage(uint32_t st,
                                           const char* gAh, const char* gAl,
                                           const char* gWh, const char* gWl,
                                           int tid) {
#pragma unroll
    for (int i = 0; i < 2; ++i) {           // A planes: 64 rows x 8 chunks
        int idx = tid + i * 256;
        int r = idx >> 3, c = idx & 7;
        uint32_t so = SWZ(r * 128 + c * 16);
        size_t go = (size_t)r * (CI * 2) + c * 16;
        cp16(st + so,          gAh + go);
        cp16(st + OFF_AL + so, gAl + go);
    }
#pragma unroll
    for (int i = 0; i < 4; ++i) {           // W planes: 128 rows x 8 chunks
        int idx = tid + i * 256;
        int r = idx >> 3, c = idx & 7;
        uint32_t so = SWZ(r * 128 + c * 16);
        size_t go = (size_t)r * (CI * 2) + c * 16;
        cp16(st + OFF_WH + so, gWh + go);
        cp16(st + OFF_WL + so, gWl + go);
    }
}

__global__ __launch_bounds__(256, 2) void so3_mma(
    const int* __restrict__ l_ind,
    float* __restrict__ out,
    int Bn) {

    extern __shared__ char smem[];
    const uint32_t sb   = smem_u32(smem);
    const uint32_t base = (sb + 1023) & ~1023u;

    const int tid  = threadIdx.x;
    const int wid  = tid >> 5;
    const int lane = tid & 31;
    const int wm   = wid & 3;          // 4 m-warps (16 rows each)
    const int wn   = wid >> 2;         // 2 n-warps (64 cols each)

    const int b0  = blockIdx.x * 64;
    const int cob = blockIdx.y * 128;
    const int M   = c_morder[blockIdx.z];
    const int gbeg = g_mg[M];
    const int gend = g_mg[M + 1];
    const int T = (gend - gbeg) * (CI / KT);   // k-tiles

    float acc[8][4];
#pragma unroll
    for (int j = 0; j < 8; ++j)
#pragma unroll
        for (int q = 0; q < 4; ++q) acc[j][q] = 0.f;

    auto srcA = [&](int t, const __nv_bfloat16* plane) -> const char* {
        int g = gbeg + (t >> 2), kc = t & 3;
        return (const char*)plane + (((size_t)g * Bn + b0) * CI + kc * KT) * 2;
    };
    auto srcW = [&](int t, const __nv_bfloat16* plane) -> const char* {
        int g = gbeg + (t >> 2), kc = t & 3;
        int w = __ldg(l_ind + g);
        return (const char*)plane + (((size_t)w * CO + cob) * CI + kc * KT) * 2;
    };

    // prologue
    load_stage(base, srcA(0, g_ah), srcA(0, g_al), srcW(0, g_wth), srcW(0, g_wtl), tid);
    CP_COMMIT();

    // ldmatrix lane addressing (fixed per thread)
    const int arow = wm * 16 + (lane & 15);
    const int acol = (lane >> 4) * 16;
    const int wrow = wn * 64 + (lane & 7) + ((lane >> 4) << 3);
    const int wcol = ((lane >> 3) & 1) * 16;

    for (int t = 0; t < T; ++t) {
        const uint32_t st = base + (uint32_t)(t & 1) * STAGE_BYTES;

        if (t + 1 < T) {
            const uint32_t stn = base + (uint32_t)((t + 1) & 1) * STAGE_BYTES;
            load_stage(stn, srcA(t + 1, g_ah), srcA(t + 1, g_al),
                       srcW(t + 1, g_wth), srcW(t + 1, g_wtl), tid);
            CP_COMMIT();
            CP_WAIT(1);
        } else {
            CP_WAIT(0);
        }
        __syncthreads();

#pragma unroll
        for (int ks = 0; ks < KT / 16; ++ks) {
            const int kb = ks * 32;
            uint32_t ah[4], al[4];
            {
                uint32_t ad = st + SWZ(arow * 128 + kb + acol);
                ldsm4(ah, ad);
                ldsm4(al, ad + OFF_AL);
            }
#pragma unroll
            for (int j = 0; j < 4; ++j) {
                uint32_t whf[4], wlf[4];
                uint32_t wd = st + OFF_WH + SWZ((wrow + j * 16) * 128 + kb + wcol);
                ldsm4(whf, wd);
                ldsm4(wlf, wd + (OFF_WL - OFF_WH));
#pragma unroll
                for (int s = 0; s < 2; ++s) {
                    float* c = acc[j * 2 + s];
                    mma16816(c, ah, whf[s * 2], whf[s * 2 + 1]);
                    mma16816(c, al, whf[s * 2], whf[s * 2 + 1]);
                    mma16816(c, ah, wlf[s * 2], wlf[s * 2 + 1]);
                }
            }
        }
        __syncthreads();
    }

    // epilogue: out[b0+.., M, cob+..] written exactly once
    const int m0 = b0 + wm * 16 + (lane >> 2);
#pragma unroll
    for (int j = 0; j < 8; ++j) {
        const int n = cob + wn * 64 + j * 8 + (lane & 3) * 2;
        float* p0 = out + ((size_t)m0 * NORD + M) * CO + n;
        float* p1 = out + ((size_t)(m0 + 8) * NORD + M) * CO + n;
        *(float2*)p0 = make_float2(acc[j][0], acc[j][1]);
        *(float2*)p1 = make_float2(acc[j][2], acc[j][3]);
    }
}

// ---------------------------------------------------------------------------
// Inputs: x, sh, weight, CG_vals, M1, M2, seg1, l_ind, seg2, num_orders_out
// ---------------------------------------------------------------------------
extern "C" void kernel_launch(void* const* d_in, const int* in_sizes, int n_in,
                              void* d_out, int out_size) {
    const float* x      = (const float*)d_in[0];
    const float* sh     = (const float*)d_in[1];
    const float* weight = (const float*)d_in[2];
    const float* CG     = (const float*)d_in[3];
    const int*   M1     = (const int*)d_in[4];
    const int*   M2     = (const int*)d_in[5];
    const int*   seg1   = (const int*)d_in[6];
    const int*   l_ind  = (const int*)d_in[7];
    const int*   seg2   = (const int*)d_in[8];
    float*       out    = (float*)d_out;

    const int nnz = in_sizes[4];
    const int G   = in_sizes[7];
    const int Bn  = in_sizes[1] / NORD;
    const int n_w = in_sizes[2] / (CI * CO);

    static bool attr_set = false;
    if (!attr_set) {
        cudaFuncSetAttribute(so3_mma, cudaFuncAttributeMaxDynamicSharedMemorySize, SMEM_DYN);
        attr_set = true;
    }

    setup_offsets<<<1, 256>>>(seg1, seg2, nnz, G);
    {
        dim3 grid(CO / 32, CI / 32, n_w);
        wsplit<<<grid, 256>>>(weight);
    }
    {
        dim3 grid(Bn / 4, 4);
        build_inter<<<grid, 256>>>(x, sh, CG, M1, M2, nnz, G, Bn);
    }
    {
        dim3 grid(Bn / 64, CO / 128, NORD);
        so3_mma<<<grid, 256, SMEM_DYN>>>(l_ind, out, Bn);
    }
}